// round 14
// baseline (speedup 1.0000x reference)
#include <cuda_runtime.h>

#define NT    64
#define BATCH 8192
#define HALF  (BATCH/2)

// Per sample: E_w = <Phi| (⊗_{j<=w} O_j) |Phi>,  Phi = CNOT-chain |⊗ phi_j>
// (bond-2 MPS).  O_j = cos^2(t) Z + sin(t)cos(t) Y - sin(t) X, t = params[1][j].
// phi_j = RY(t1) RX(t1) RY(x_j)|0>, t1 = params[0][j].
// Hermitian boundary in trace/difference form (|f0|^2+|f1|^2 = 1):
//   E = T + 4 gr Pr (emitted & = next D/cc), T' = cc(Z D - 4 gi Pi), D' = cc E,
//   N01 = (gr T + Pr, gi D + Z Pi), P' = (a+ib) N01;
//   a=-sin t, b=sin t cos t, cc=cos^2 t.  Final E_11 = T + 2 Pr.
// TWO independent samples per thread (s=0: row b; s=1: row b+HALF) —
// halves the block count (64 blocks) while the two dependency chains
// interleave in the abundant issue slack (issue was ~16%).
__global__ void __launch_bounds__(NT)
qexp_kernel(const float* __restrict__ x, const float* __restrict__ params,
            const float* __restrict__ hw, const float* __restrict__ hb,
            float* __restrict__ out)
{
    const int b = blockIdx.x * NT + threadIdx.x;

    // ---- issue ALL loads up front (one memory epoch, MLP ~16) ----
    const float4* xv0 = (const float4*)(x + b * 12);            // sample 0
    const float4* xv1 = (const float4*)(x + (b + HALF) * 12);   // sample 1
    const float4 a0 = xv0[0], a1 = xv0[1], a2 = xv0[2];
    const float4 b0 = xv1[0], b1 = xv1[1], b2 = xv1[2];
    const float4* pv = (const float4*)params;                   // 24 floats (broadcast)
    const float4 p0 = pv[0], p1 = pv[1], p2 = pv[2];
    const float4 p3 = pv[3], p4 = pv[4], p5 = pv[5];
    const float4* wv = (const float4*)hw;                       // 12 floats (broadcast)
    const float4 w0 = wv[0], w1 = wv[1], w2 = wv[2];
    const float bias = hb[0];

    const float xa[2][12] = {
        { a0.x,a0.y,a0.z,a0.w, a1.x,a1.y,a1.z,a1.w, a2.x,a2.y,a2.z,a2.w },
        { b0.x,b0.y,b0.z,b0.w, b1.x,b1.y,b1.z,b1.w, b2.x,b2.y,b2.z,b2.w } };
    const float th1[12] = { p0.x,p0.y,p0.z,p0.w, p1.x,p1.y,p1.z,p1.w,
                            p2.x,p2.y,p2.z,p2.w };
    const float th2[12] = { p3.x,p3.y,p3.z,p3.w, p4.x,p4.y,p4.z,p4.w,
                            p5.x,p5.y,p5.z,p5.w };
    const float hwa[12] = { w0.x,w0.y,w0.z,w0.w, w1.x,w1.y,w1.z,w1.w,
                            w2.x,w2.y,w2.z,w2.w };

    // ---- per-wire precompute: param trig shared, per-sample x trig ----
    float Zq[2][12], Gr[2][12], Gr4[2][12], Gi[2][12], Gi4[2][12];
    float Oa[12], Ob[12], Oc[12];
    #pragma unroll
    for (int j = 0; j < 12; j++){
        float s1, c1; __sincosf(0.5f * th1[j], &s1, &c1);
        float s2, c2; __sincosf(th2[j], &s2, &c2);        // full angle for O
        Oa[j] = -s2; Ob[j] = s2 * c2; Oc[j] = c2 * c2;
        #pragma unroll
        for (int s = 0; s < 2; s++){
            float sx, cx; __sincosf(0.5f * xa[s][j], &sx, &cx);
            // phi_j = RY(t1) RX(t1) (cx, sx)
            const float f0r =  c1 * (c1 * cx - s1 * sx);
            const float f0i =  s1 * (s1 * cx - c1 * sx);
            const float f1r =  c1 * (s1 * cx + c1 * sx);
            const float f1i = -s1 * (s1 * sx + c1 * cx);
            const float A = fmaf(f0r, f0r, f0i * f0i);
            const float B = fmaf(f1r, f1r, f1i * f1i);
            Zq[s][j] = A - B;                              // |f0|^2 - |f1|^2
            const float gr = fmaf(f0r, f1r,  f0i * f1i);   // Re(f0 conj f1)
            const float gi = fmaf(f0i, f1r, -f0r * f1i);   // Im(f0 conj f1)
            Gr[s][j] = gr; Gr4[s][j] = 4.f * gr;
            Gi[s][j] = gi; Gi4[s][j] = -4.f * gi;
        }
    }

    // ---- two interleaved serial sweeps in (T, D, Pr, Pi) form ----
    float T[2]  = {1.f, 1.f}, Dd[2] = {1.f, 1.f};
    float Pr[2] = {0.f, 0.f}, Pi[2] = {0.f, 0.f};
    float acc[2] = {bias, bias};

    #pragma unroll
    for (int j = 0; j < 12; j++){
        const float cc = Oc[j], a = Oa[j], bb = Ob[j];
        #pragma unroll
        for (int s = 0; s < 2; s++){
            const float E = fmaf(Gr4[s][j], Pr[s], T[s]);  // = E_{j-1}
            if (j > 0) acc[s] = fmaf(hwa[j-1], E, acc[s]);

            const float newT = cc * fmaf(Zq[s][j], Dd[s], Gi4[s][j] * Pi[s]);
            const float newD = cc * E;
            const float N01r = fmaf(Gr[s][j], T[s], Pr[s]);
            const float N01i = fmaf(Gi[s][j], Dd[s], Zq[s][j] * Pi[s]);
            Pr[s] = fmaf(a, N01r, -bb * N01i);
            Pi[s] = fmaf(a, N01i,  bb * N01r);
            T[s] = newT; Dd[s] = newD;
        }
    }

    #pragma unroll
    for (int s = 0; s < 2; s++){
        const float E11 = fmaf(2.f, Pr[s], T[s]);          // empty suffix
        acc[s] = fmaf(hwa[11], E11, acc[s]);
    }

    out[b]        = acc[0];
    out[b + HALF] = acc[1];
}

extern "C" void kernel_launch(void* const* d_in, const int* in_sizes, int n_in,
                              void* d_out, int out_size)
{
    const float* x      = (const float*)d_in[0];   // [8192,12]
    const float* params = (const float*)d_in[1];   // [2,12]
    const float* hw     = (const float*)d_in[2];   // [1,12]
    const float* hb     = (const float*)d_in[3];   // [1]
    float* out          = (float*)d_out;           // [8192,1]
    (void)in_sizes; (void)n_in; (void)out_size;

    qexp_kernel<<<HALF / NT, NT>>>(x, params, hw, hb, out);
}